// round 8
// baseline (speedup 1.0000x reference)
#include <cuda_runtime.h>
#include <cstdint>

#define B_DIM 512
#define F_DIM 784
#define R_DIM 512
#define C_DIM 16
#define D_DIM 49
#define HALF_LOG_2PI 0.9189385332046727f

// Scratch (allocation-free rule: __device__ global)
__device__ float g_xT[F_DIM * B_DIM];               // [f][b] (1.6MB, L2-resident)

// ---------------------------------------------------------------------------
// packed f32x2 FMA (Blackwell FFMA2 — only reachable via PTX)
// ---------------------------------------------------------------------------
__device__ __forceinline__ unsigned long long fma2(unsigned long long a,
                                                   unsigned long long b,
                                                   unsigned long long c) {
    unsigned long long d;
    asm("fma.rn.f32x2 %0, %1, %2, %3;" : "=l"(d) : "l"(a), "l"(b), "l"(c));
    return d;
}
__device__ __forceinline__ void unpack2(unsigned long long v, float& lo, float& hi) {
    unsigned int l, h;
    asm("mov.b64 {%0, %1}, %2;" : "=r"(l), "=r"(h) : "l"(v));
    lo = __uint_as_float(l);
    hi = __uint_as_float(h);
}
__device__ __forceinline__ uint32_t smem_u32(const void* p) {
    uint32_t a;
    asm("{ .reg .u64 t; cvta.to.shared.u64 t, %1; cvt.u32.u64 %0, t; }" : "=r"(a) : "l"(p));
    return a;
}
__device__ __forceinline__ void cp_async16(uint32_t dst, const void* src) {
    asm volatile("cp.async.cg.shared.global [%0], [%1], 16;" :: "r"(dst), "l"(src));
}

// ---------------------------------------------------------------------------
// Kernel 1: transpose x[b][f] -> xT[f][b].
// ---------------------------------------------------------------------------
__global__ void __launch_bounds__(256) transpose_kernel(const float* __restrict__ x) {
    __shared__ float tile[32][33];
    int fx = blockIdx.x * 32 + threadIdx.x;
    #pragma unroll
    for (int k = 0; k < 32; k += 8) {
        int b = blockIdx.y * 32 + threadIdx.y + k;
        if (fx < F_DIM) tile[threadIdx.y + k][threadIdx.x] = x[b * F_DIM + fx];
    }
    __syncthreads();
    int b_out = blockIdx.y * 32 + threadIdx.x;
    #pragma unroll
    for (int k = 0; k < 32; k += 8) {
        int f = blockIdx.x * 32 + threadIdx.y + k;
        if (f < F_DIM) g_xT[f * B_DIM + b_out] = tile[threadIdx.x][threadIdx.y + k];
    }
}

// ---------------------------------------------------------------------------
// Kernel 2: fused prep + main. Block = (r, 128-b quarter). 128 threads,
// thread tile 8b x 2c (4 f32x2 b-pairs x 2 c). Per d: 4 LDS.128 + 16 FFMA2.
// grid = 512 r x 4 quarters = 2048 blocks -> streams at high occupancy.
//
// Coefficients computed per-block (4x duplicated per r — trivial work),
// loc/scale read directly coalesced in native [c][d] order; contrib scratch
// reuses xs[1] (chunk-1 gather is issued only after the base reduction).
//
// smem layouts:
//   x rows: 128 floats (512B) unpadded — warp touches 4 distinct 16B lines
//           at banks 0-3 / 8-11 / 16-19 / 24-27 (conflict-free broadcast x8).
//   A/B rows: ABROW=36 floats (144B = 9x16 -> every row 16B-aligned for
//           ulonglong2 loads). Hot loads hit banks {4h..4h+3}, h=0..7 ->
//           banks 0..31 exactly, conflict-free.
// ---------------------------------------------------------------------------
#define XROW 128            // floats per d-row (quarter of B)
#define ABROW 36            // padded coeff row stride (16B-aligned rows!)
#define DCHUNK 7
#define NCHUNK 7

__global__ void __launch_bounds__(128, 10) main_kernel(const float* __restrict__ loc,
                                                       const float* __restrict__ scale,
                                                       const int* __restrict__ mask,
                                                       float* __restrict__ out) {
    int r   = blockIdx.x;
    int bq0 = blockIdx.y * 128;           // b offset of this quarter
    int tid = threadIdx.x;

    __shared__ __align__(16) float sA2[D_DIM * ABROW];    // [d][c dup pairs]
    __shared__ __align__(16) float sB2[D_DIM * ABROW];
    __shared__ __align__(16) float xs[2][DCHUNK * XROW];
    __shared__ int   smask[D_DIM];
    __shared__ float sbase[C_DIM];

    // ---- mask first (gather addresses) ----
    if (tid < D_DIM) smask[tid] = mask[r * D_DIM + tid];
    __syncthreads();

    const float* xTp = g_xT;
    uint32_t xs_base[2] = { smem_u32(&xs[0][0]), smem_u32(&xs[1][0]) };

    // ---- chunk 0 gather in flight while we do the coefficient math ----
    #pragma unroll
    for (int i = tid; i < DCHUNK * 32; i += 128) {
        int s = i >> 5, q = i & 31;
        cp_async16(xs_base[0] + (uint32_t)(s * XROW + q * 4) * 4u,
                   xTp + (size_t)smask[s] * B_DIM + bq0 + q * 4);
    }
    asm volatile("cp.async.commit_group;");

    // ---- coefficients: coalesced global reads in native [c][d] order ----
    float* scontrib = &xs[1][0];          // 784 <= 896 floats; free until chunk 1
    #pragma unroll
    for (int i = tid; i < 784; i += 128) {
        int c = i / D_DIM;
        int d = i - c * D_DIM;
        float lc = loc[r * 784 + i];
        float sc = scale[r * 784 + i];
        float A, Bv, contrib;
        if (sc > 0.0f) {
            float inv = 1.0f / sc;
            float w = inv * inv;
            A = -0.5f * w;
            Bv = w * lc;
            contrib = -0.5f * w * lc * lc - __logf(sc) - HALF_LOG_2PI;
        } else {
            A = 0.0f; Bv = 0.0f; contrib = 0.0f;   // reference zeroes NaN logp
        }
        sA2[d * ABROW + c * 2]     = A;
        sA2[d * ABROW + c * 2 + 1] = A;
        sB2[d * ABROW + c * 2]     = Bv;
        sB2[d * ABROW + c * 2 + 1] = Bv;
        scontrib[i] = contrib;            // [c][d] contiguous
    }
    __syncthreads();

    // ---- base[c] reduction: 8 threads per c, shuffle within 8-lane groups ----
    {
        int c = tid >> 3;            // 0..15
        int l = tid & 7;
        float s = 0.0f;
        for (int d = l; d < D_DIM; d += 8) s += scontrib[c * D_DIM + d];
        s += __shfl_down_sync(0xffffffffu, s, 4, 8);
        s += __shfl_down_sync(0xffffffffu, s, 2, 8);
        s += __shfl_down_sync(0xffffffffu, s, 1, 8);
        if (l == 0) sbase[c] = s;
    }
    __syncthreads();    // scontrib reads done -> xs[1] free for chunk 1

    // ---- chunk 1 gather ----
    #pragma unroll
    for (int i = tid; i < DCHUNK * 32; i += 128) {
        int s = i >> 5, q = i & 31;
        cp_async16(xs_base[1] + (uint32_t)(s * XROW + q * 4) * 4u,
                   xTp + (size_t)smask[DCHUNK + s] * B_DIM + bq0 + q * 4);
    }
    asm volatile("cp.async.commit_group;");

    int g = tid >> 3;    // 0..15 -> 8-b segment
    int h = tid & 7;     // 0..7  -> c pair {2h, 2h+1}

    unsigned long long acc[4][2];
    #pragma unroll
    for (int p = 0; p < 4; ++p) { acc[p][0] = 0ull; acc[p][1] = 0ull; }

    for (int k = 0; k < NCHUNK; ++k) {
        if (k < NCHUNK - 1) asm volatile("cp.async.wait_group 1;");
        else                asm volatile("cp.async.wait_group 0;");
        __syncthreads();                     // buf[k&1] visible to all

        const float* xb = &xs[k & 1][g * 8];
        const float* Ab = sA2 + k * (DCHUNK * ABROW) + h * 4;
        const float* Bb = sB2 + k * (DCHUNK * ABROW) + h * 4;

        #pragma unroll
        for (int dd = 0; dd < DCHUNK; ++dd) {
            ulonglong2 xa = *reinterpret_cast<const ulonglong2*>(xb + dd * XROW);
            ulonglong2 xc = *reinterpret_cast<const ulonglong2*>(xb + dd * XROW + 4);
            ulonglong2 aa = *reinterpret_cast<const ulonglong2*>(Ab + dd * ABROW);
            ulonglong2 ba = *reinterpret_cast<const ulonglong2*>(Bb + dd * ABROW);
            unsigned long long x2[4] = {xa.x, xa.y, xc.x, xc.y};
            unsigned long long a2[2] = {aa.x, aa.y};
            unsigned long long b2[2] = {ba.x, ba.y};
            #pragma unroll
            for (int j = 0; j < 2; ++j)
                #pragma unroll
                for (int p = 0; p < 4; ++p) {
                    unsigned long long t = fma2(a2[j], x2[p], b2[j]);
                    acc[p][j] = fma2(x2[p], t, acc[p][j]);
                }
        }
        __syncthreads();                     // done reading buf[k&1]

        if (k + 2 < NCHUNK) {                // refill buf[k&1] with chunk k+2
            int d0 = (k + 2) * DCHUNK;
            #pragma unroll
            for (int i = tid; i < DCHUNK * 32; i += 128) {
                int s = i >> 5, q = i & 31;
                cp_async16(xs_base[k & 1] + (uint32_t)(s * XROW + q * 4) * 4u,
                           xTp + (size_t)smask[d0 + s] * B_DIM + bq0 + q * 4);
            }
            asm volatile("cp.async.commit_group;");
        }
    }

    // ---- epilogue: unpack pairs, add base, store ----
    float bb0 = sbase[2 * h];
    float bb1 = sbase[2 * h + 1];
    int b0 = bq0 + g * 8;

    #pragma unroll
    for (int p = 0; p < 4; ++p) {
        float lo0, hi0, lo1, hi1;
        unpack2(acc[p][0], lo0, hi0);
        unpack2(acc[p][1], lo1, hi1);
        size_t row = (size_t)(b0 + 2 * p) * (R_DIM * C_DIM) + r * C_DIM + 2 * h;
        *reinterpret_cast<float2*>(out + row) = make_float2(lo0 + bb0, lo1 + bb1);
        *reinterpret_cast<float2*>(out + row + (R_DIM * C_DIM)) = make_float2(hi0 + bb0, hi1 + bb1);
    }
}

// ---------------------------------------------------------------------------
extern "C" void kernel_launch(void* const* d_in, const int* in_sizes, int n_in,
                              void* d_out, int out_size) {
    const float* x     = (const float*)d_in[0];
    const int*   mask  = (const int*)d_in[1];
    const float* loc   = (const float*)d_in[2];
    const float* scale = (const float*)d_in[3];
    float* out = (float*)d_out;

    transpose_kernel<<<dim3((F_DIM + 31) / 32, B_DIM / 32), dim3(32, 8)>>>(x);
    main_kernel<<<dim3(R_DIM, 4), 128>>>(loc, scale, mask, out);
}

// round 9
// speedup vs baseline: 1.0696x; 1.0696x over previous
#include <cuda_runtime.h>
#include <cstdint>

#define B_DIM 512
#define F_DIM 784
#define R_DIM 512
#define C_DIM 16
#define D_DIM 49
#define HALF_LOG_2PI 0.9189385332046727f

// Scratch (allocation-free rule: __device__ global)
__device__ float g_xT[F_DIM * B_DIM];               // [f][b] (1.6MB, L2-resident)

// ---------------------------------------------------------------------------
// packed f32x2 helpers (Blackwell FFMA2 — only reachable via PTX)
// ---------------------------------------------------------------------------
__device__ __forceinline__ unsigned long long fma2(unsigned long long a,
                                                   unsigned long long b,
                                                   unsigned long long c) {
    unsigned long long d;
    asm("fma.rn.f32x2 %0, %1, %2, %3;" : "=l"(d) : "l"(a), "l"(b), "l"(c));
    return d;
}
__device__ __forceinline__ unsigned long long dup2(float v) {   // (v, v)
    unsigned long long r;
    asm("mov.b64 %0, {%1, %1};" : "=l"(r) : "f"(v));
    return r;
}
__device__ __forceinline__ void unpack2(unsigned long long v, float& lo, float& hi) {
    unsigned int l, h;
    asm("mov.b64 {%0, %1}, %2;" : "=r"(l), "=r"(h) : "l"(v));
    lo = __uint_as_float(l);
    hi = __uint_as_float(h);
}
__device__ __forceinline__ uint32_t smem_u32(const void* p) {
    uint32_t a;
    asm("{ .reg .u64 t; cvta.to.shared.u64 t, %1; cvt.u32.u64 %0, t; }" : "=r"(a) : "l"(p));
    return a;
}
__device__ __forceinline__ void cp_async16(uint32_t dst, const void* src) {
    asm volatile("cp.async.cg.shared.global [%0], [%1], 16;" :: "r"(dst), "l"(src));
}

// ---------------------------------------------------------------------------
// Kernel 1: transpose x[b][f] -> xT[f][b].
// ---------------------------------------------------------------------------
__global__ void __launch_bounds__(256) transpose_kernel(const float* __restrict__ x) {
    __shared__ float tile[32][33];
    int fx = blockIdx.x * 32 + threadIdx.x;
    #pragma unroll
    for (int k = 0; k < 32; k += 8) {
        int b = blockIdx.y * 32 + threadIdx.y + k;
        if (fx < F_DIM) tile[threadIdx.y + k][threadIdx.x] = x[b * F_DIM + fx];
    }
    __syncthreads();
    int b_out = blockIdx.y * 32 + threadIdx.x;
    #pragma unroll
    for (int k = 0; k < 32; k += 8) {
        int f = blockIdx.x * 32 + threadIdx.y + k;
        if (f < F_DIM) g_xT[f * B_DIM + b_out] = tile[threadIdx.x][threadIdx.y + k];
    }
}

// ---------------------------------------------------------------------------
// Kernel 2: fused prep + main, c-PACKED f32x2 lanes.
// Block = (r, 256-b half). 128 threads; thread tile 8b x 4c, f32x2 lanes
// hold (c, c+1) so A/B load UN-duplicated ([d][16] rows, 1 LDS.128 each).
// x loaded scalar and duplicated to (x,x) via mov.b64 on the idle alu pipe.
// Per warp per d: 4 LDS.128 (16 smem cyc) vs 32 FFMA2 (16 fma cyc) —
// balanced at the chip floor on both pipes. acc = 16 u64 = 32 regs.
// grid = 1024, 7 blocks/SM -> single wave, ~44% occ.
//
// x smem: rows of 256 floats, no padding. Thread g loads 2 LDS.128 at
// g*16B and g*16B+512B: 8 distinct g per warp -> banks 0..31 exactly.
// Thread's b: {g*4+0..3} and {128+g*4+0..3}.
// ---------------------------------------------------------------------------
#define XROW 256            // floats per d-row (half of B)
#define ABROW 16            // [d][16 c] rows, 64B (16B-aligned)
#define DCHUNK 7
#define NCHUNK 7

__global__ void __launch_bounds__(128, 7) main_kernel(const float* __restrict__ loc,
                                                      const float* __restrict__ scale,
                                                      const int* __restrict__ mask,
                                                      float* __restrict__ out) {
    int r   = blockIdx.x;
    int bq0 = blockIdx.y * 256;           // b offset of this half
    int tid = threadIdx.x;

    __shared__ __align__(16) float sA[D_DIM * ABROW];    // [d][c], -0.5/s^2
    __shared__ __align__(16) float sB[D_DIM * ABROW];    // [d][c], loc/s^2
    __shared__ __align__(16) float xs[2][DCHUNK * XROW];
    __shared__ int   smask[D_DIM];
    __shared__ float sbase[C_DIM];

    // ---- mask first (gather addresses) ----
    if (tid < D_DIM) smask[tid] = mask[r * D_DIM + tid];
    __syncthreads();

    const float* xTp = g_xT;
    uint32_t xs_base[2] = { smem_u32(&xs[0][0]), smem_u32(&xs[1][0]) };

    // ---- chunk 0 gather in flight while we do the coefficient math ----
    // 7 rows x 64 float4 = 448 cp.async
    for (int i = tid; i < DCHUNK * 64; i += 128) {
        int s = i >> 6, q = i & 63;
        cp_async16(xs_base[0] + (uint32_t)(s * XROW + q * 4) * 4u,
                   xTp + (size_t)smask[s] * B_DIM + bq0 + q * 4);
    }
    asm volatile("cp.async.commit_group;");

    // ---- coefficients: coalesced global reads in native [c][d] order ----
    float* scontrib = &xs[1][0];          // 784 <= 1792 floats; free until chunk 1
    #pragma unroll
    for (int i = tid; i < 784; i += 128) {
        int c = i / D_DIM;
        int d = i - c * D_DIM;
        float lc = loc[r * 784 + i];
        float sc = scale[r * 784 + i];
        float A, Bv, contrib;
        if (sc > 0.0f) {
            float inv = 1.0f / sc;
            float w = inv * inv;
            A = -0.5f * w;
            Bv = w * lc;
            contrib = -0.5f * w * lc * lc - __logf(sc) - HALF_LOG_2PI;
        } else {
            A = 0.0f; Bv = 0.0f; contrib = 0.0f;   // reference zeroes NaN logp
        }
        sA[d * ABROW + c] = A;
        sB[d * ABROW + c] = Bv;
        scontrib[i] = contrib;            // [c][d] contiguous
    }
    __syncthreads();

    // ---- base[c] reduction: 8 threads per c, shuffle within 8-lane groups ----
    {
        int c = tid >> 3;            // 0..15
        int l = tid & 7;
        float s = 0.0f;
        for (int d = l; d < D_DIM; d += 8) s += scontrib[c * D_DIM + d];
        s += __shfl_down_sync(0xffffffffu, s, 4, 8);
        s += __shfl_down_sync(0xffffffffu, s, 2, 8);
        s += __shfl_down_sync(0xffffffffu, s, 1, 8);
        if (l == 0) sbase[c] = s;
    }
    __syncthreads();    // scontrib reads done -> xs[1] free for chunk 1

    // ---- chunk 1 gather ----
    for (int i = tid; i < DCHUNK * 64; i += 128) {
        int s = i >> 6, q = i & 63;
        cp_async16(xs_base[1] + (uint32_t)(s * XROW + q * 4) * 4u,
                   xTp + (size_t)smask[DCHUNK + s] * B_DIM + bq0 + q * 4);
    }
    asm volatile("cp.async.commit_group;");

    int g = tid >> 2;    // 0..31 -> b positions g*4+{0..3} and 128+g*4+{0..3}
    int h = tid & 3;     // 0..3  -> c group 4h..4h+3

    unsigned long long acc[8][2];        // [b][c-pair], 32 regs
    #pragma unroll
    for (int p = 0; p < 8; ++p) { acc[p][0] = 0ull; acc[p][1] = 0ull; }

    for (int k = 0; k < NCHUNK; ++k) {
        if (k < NCHUNK - 1) asm volatile("cp.async.wait_group 1;");
        else                asm volatile("cp.async.wait_group 0;");
        __syncthreads();                     // buf[k&1] visible to all

        const float* xb = &xs[k & 1][g * 4];
        const float* Ab = sA + k * (DCHUNK * ABROW) + h * 4;
        const float* Bb = sB + k * (DCHUNK * ABROW) + h * 4;

        #pragma unroll
        for (int dd = 0; dd < DCHUNK; ++dd) {
            const float* xr = xb + dd * XROW;
            float4 xv0 = *reinterpret_cast<const float4*>(xr);         // b = g*4+..
            float4 xv1 = *reinterpret_cast<const float4*>(xr + 128);   // b = 128+g*4+..
            ulonglong2 av = *reinterpret_cast<const ulonglong2*>(Ab + dd * ABROW);
            ulonglong2 bv = *reinterpret_cast<const ulonglong2*>(Bb + dd * ABROW);
            float xf[8] = {xv0.x, xv0.y, xv0.z, xv0.w, xv1.x, xv1.y, xv1.z, xv1.w};
            unsigned long long a2[2] = {av.x, av.y};
            unsigned long long b2[2] = {bv.x, bv.y};
            #pragma unroll
            for (int p = 0; p < 8; ++p) {
                unsigned long long xd = dup2(xf[p]);    // alu pipe (idle)
                #pragma unroll
                for (int j = 0; j < 2; ++j) {
                    unsigned long long t = fma2(a2[j], xd, b2[j]);
                    acc[p][j] = fma2(xd, t, acc[p][j]);
                }
            }
        }
        __syncthreads();                     // done reading buf[k&1]

        if (k + 2 < NCHUNK) {                // refill buf[k&1] with chunk k+2
            int d0 = (k + 2) * DCHUNK;
            for (int i = tid; i < DCHUNK * 64; i += 128) {
                int s = i >> 6, q = i & 63;
                cp_async16(xs_base[k & 1] + (uint32_t)(s * XROW + q * 4) * 4u,
                           xTp + (size_t)smask[d0 + s] * B_DIM + bq0 + q * 4);
            }
            asm volatile("cp.async.commit_group;");
        }
    }

    // ---- epilogue: unpack c-pairs, add base, store one float4 per b ----
    float bb0 = sbase[4 * h];
    float bb1 = sbase[4 * h + 1];
    float bb2 = sbase[4 * h + 2];
    float bb3 = sbase[4 * h + 3];

    #pragma unroll
    for (int p = 0; p < 8; ++p) {
        int bl = (p < 4) ? (g * 4 + p) : (128 + g * 4 + (p - 4));
        float c0, c1, c2, c3;
        unpack2(acc[p][0], c0, c1);
        unpack2(acc[p][1], c2, c3);
        float4 o = make_float4(c0 + bb0, c1 + bb1, c2 + bb2, c3 + bb3);
        *reinterpret_cast<float4*>(out + (size_t)(bq0 + bl) * (R_DIM * C_DIM)
                                   + r * C_DIM + 4 * h) = o;
    }
}

// ---------------------------------------------------------------------------
extern "C" void kernel_launch(void* const* d_in, const int* in_sizes, int n_in,
                              void* d_out, int out_size) {
    const float* x     = (const float*)d_in[0];
    const int*   mask  = (const int*)d_in[1];
    const float* loc   = (const float*)d_in[2];
    const float* scale = (const float*)d_in[3];
    float* out = (float*)d_out;

    transpose_kernel<<<dim3((F_DIM + 31) / 32, B_DIM / 32), dim3(32, 8)>>>(x);
    main_kernel<<<dim3(R_DIM, 2), 128>>>(loc, scale, mask, out);
}